// round 4
// baseline (speedup 1.0000x reference)
#include <cuda_runtime.h>
#include <cuda_bf16.h>

// Problem constants
#define HH 128
#define WW 128
#define NN (HH*WW)          // 16384 nodes per batch
#define EE (2*NN)           // 32768 edges per batch
#define BB 2
#define NBUCK 4096

// ---------------- device globals (no allocation allowed) ----------------
__device__ unsigned short g_parent[BB][NN];
__device__ unsigned short g_size  [BB][NN];
__device__ unsigned short g_nz    [BB][NN];
__device__ unsigned char  g_label [BB][NN];
__device__ unsigned int   g_cnt   [BB][NN][32];   // 64 labels as u16 pairs per u32
__device__ unsigned long long g_sorted[BB][EE];   // (aff_bits<<32)|edge_idx, ascending
__device__ double g_loss[BB];
__device__ int g_is64;

// ---------------- dtype detection for groundtruth (int32 vs int64) ------
// If int64: every odd 32-bit word of the first 1024 entries is 0 (labels<64).
// If int32: odd words are random labels; all-zero has prob (1/64)^1024 ~ 0.
__global__ void detect_kernel(const int* gt32) {
    __shared__ int s_any;
    if (threadIdx.x == 0) s_any = 0;
    __syncthreads();
    int any = 0;
    for (int i = threadIdx.x; i < 1024; i += blockDim.x) any |= gt32[2*i + 1];
    if (any) atomicOr(&s_any, 1);
    __syncthreads();
    if (threadIdx.x == 0) g_is64 = (s_any == 0) ? 1 : 0;
}

// ---------------- init union-find + histograms ---------------------------
__global__ void init_kernel(const void* gt) {
    int t = blockIdx.x * blockDim.x + threadIdx.x;
    if (t >= BB * NN) return;
    int b = t >> 14, n = t & (NN - 1);
    int l;
    if (g_is64) l = (int)((const long long*)gt)[b * NN + n];
    else        l = ((const int*)gt)[b * NN + n];
    g_parent[b][n] = (unsigned short)n;
    g_size[b][n]   = 1;
    g_nz[b][n]     = (l != 0) ? 1 : 0;
    g_label[b][n]  = (unsigned char)l;
    unsigned* row = g_cnt[b][n];
    #pragma unroll
    for (int w = 0; w < 32; w++) row[w] = 0u;
    row[l >> 1] = (l & 1) ? (1u << 16) : 1u;
    if (t < BB) g_loss[t] = 0.0;
}

// ---------------- bucket sort (per batch block) ---------------------------
// aff uniform in [0,1) -> bucket = floor(a*4096) is monotone in a and
// uniformly occupied (~8/bucket). Within-bucket order fixed by insertion
// sort on the packed (aff_bits, idx) u64 -> fully deterministic.
__global__ void __launch_bounds__(1024) sort_kernel(const float* __restrict__ aff) {
    int b = blockIdx.x;
    const float* a = aff + b * EE;
    __shared__ unsigned hist[NBUCK];
    __shared__ unsigned offs[NBUCK + 1];
    __shared__ unsigned warp_sums[32];
    int tid = threadIdx.x;

    for (int i = tid; i < NBUCK; i += 1024) hist[i] = 0;
    __syncthreads();

    for (int e = tid; e < EE; e += 1024) {
        int bk = min(NBUCK - 1, (int)(a[e] * (float)NBUCK));
        atomicAdd(&hist[bk], 1u);
    }
    __syncthreads();

    // exclusive scan of hist[4096]: 4 buckets per thread
    unsigned s0 = hist[4*tid], s1 = hist[4*tid+1], s2 = hist[4*tid+2], s3 = hist[4*tid+3];
    unsigned tsum = s0 + s1 + s2 + s3;
    unsigned inc = tsum;
    #pragma unroll
    for (int o = 1; o < 32; o <<= 1) {
        unsigned v = __shfl_up_sync(0xffffffffu, inc, o);
        if ((tid & 31) >= o) inc += v;
    }
    if ((tid & 31) == 31) warp_sums[tid >> 5] = inc;
    __syncthreads();
    if (tid < 32) {
        unsigned v = warp_sums[tid];
        unsigned iv = v;
        #pragma unroll
        for (int o = 1; o < 32; o <<= 1) {
            unsigned t2 = __shfl_up_sync(0xffffffffu, iv, o);
            if (tid >= o) iv += t2;
        }
        warp_sums[tid] = iv - v;  // exclusive warp base
    }
    __syncthreads();
    unsigned base = warp_sums[tid >> 5] + inc - tsum;
    offs[4*tid]   = base;
    offs[4*tid+1] = base + s0;
    offs[4*tid+2] = base + s0 + s1;
    offs[4*tid+3] = base + s0 + s1 + s2;
    __syncthreads();
    for (int i = tid; i < NBUCK; i += 1024) hist[i] = offs[i];  // scatter cursors
    if (tid == 0) offs[NBUCK] = EE;
    __syncthreads();

    for (int e = tid; e < EE; e += 1024) {
        float av = a[e];
        int bk = min(NBUCK - 1, (int)(av * (float)NBUCK));
        unsigned pos = atomicAdd(&hist[bk], 1u);
        g_sorted[b][pos] = ((unsigned long long)__float_as_uint(av) << 32) | (unsigned)e;
    }
    __syncthreads();

    // per-bucket insertion sort (ascending by packed u64)
    unsigned long long* arr = g_sorted[b];
    for (int bk = tid; bk < NBUCK; bk += 1024) {
        int s = (int)offs[bk], epos = (int)offs[bk + 1];
        for (int k = s + 1; k < epos; k++) {
            unsigned long long key = arr[k];
            int j = k - 1;
            while (j >= s && arr[j] > key) { arr[j + 1] = arr[j]; j--; }
            arr[j + 1] = key;
        }
    }
}

// ---------------- Kruskal + MALIS accumulation (one warp per batch) -------
__global__ void __launch_bounds__(32) kruskal_kernel() {
    const unsigned FULL = 0xffffffffu;
    int b = blockIdx.x;
    int lane = threadIdx.x;
    unsigned short* parent = g_parent[b];
    unsigned short* size_  = g_size[b];
    unsigned short* nz_    = g_nz[b];
    unsigned char*  lab_   = g_label[b];
    unsigned (*cnt)[32]    = g_cnt[b];
    const unsigned long long* srt = g_sorted[b];

    double loss = 0.0;

    for (int base = EE - 32; base >= 0; base -= 32) {
        unsigned long long pk = srt[base + lane];
        // process edges in DESCENDING affinity order: i = 31 .. 0
        for (int i = 31; i >= 0; i--) {
            unsigned long long p = __shfl_sync(FULL, pk, i);
            unsigned idx = (unsigned)p;
            float a = __uint_as_float((unsigned)(p >> 32));
            int c  = (int)(idx >> 14);
            int uu = (int)(idx & (NN - 1));
            int vv;
            if (c == 0) vv = (uu < NN - WW) ? uu + WW : -1;      // vertical edge
            else        vv = ((uu & (WW - 1)) != WW - 1) ? uu + 1 : -1; // horizontal
            if (vv < 0) continue;  // boundary no-op (uniform branch)

            // parallel finds with path halving: lane0 -> uu, lane1 -> vv
            int root = 0;
            if (lane < 2) {
                int x = lane ? vv : uu;
                for (;;) {
                    int pa = parent[x];
                    if (pa == x) break;
                    int g = parent[pa];
                    parent[x] = (unsigned short)g;
                    x = g;
                }
                root = x;
            }
            int ru = __shfl_sync(FULL, root, 0);
            int rv = __shfl_sync(FULL, root, 1);
            if (ru == rv) continue;

            int su = size_[ru], sv = size_[rv];
            int tu = nz_[ru],   tv = nz_[rv];
            int big   = (su >= sv) ? ru : rv;
            int small = ru + rv - big;

            unsigned long long npos = 0;
            if (su > 1 && sv > 1) {
                // full 64-label dot via warp (u16 pairs packed in u32 per lane)
                unsigned wu = cnt[ru][lane], wv = cnt[rv][lane];
                unsigned lou = wu & 0xffffu, hiu = wu >> 16;
                unsigned lov = wv & 0xffffu, hiv = wv >> 16;
                if (lane == 0) lou = 0;  // exclude background label 0
                unsigned long long part = (unsigned long long)lou * lov
                                        + (unsigned long long)hiu * hiv;
                #pragma unroll
                for (int o = 16; o; o >>= 1)
                    part += __shfl_down_sync(FULL, part, o);
                npos = part;               // valid on lane 0
                cnt[big][lane] = wu + wv;  // packed u16 add (counts <= 16384, no carry)
            } else if (lane == 0) {
                if (su == 1 && sv == 1) {
                    int lu = lab_[ru], lv = lab_[rv];
                    npos = (lu > 0 && lu == lv) ? 1ull : 0ull;
                    // big == ru here; its row already holds one-hot(lu); add one-hot(lv)
                    if (lv > 0) cnt[ru][lv >> 1] += (lv & 1) ? (1u << 16) : 1u;
                } else {
                    int sroot = (su == 1) ? ru : rv;   // singleton side (== small)
                    int oroot = (su == 1) ? rv : ru;   // multi side (== big)
                    int ls = lab_[sroot];
                    if (ls > 0) {
                        unsigned w = cnt[oroot][ls >> 1];
                        npos = (ls & 1) ? (w >> 16) : (w & 0xffffu);
                        cnt[oroot][ls >> 1] = w + ((ls & 1) ? (1u << 16) : 1u);
                    }
                }
            }

            if (lane == 0) {
                unsigned long long nneg = (unsigned long long)tu * (unsigned long long)tv - npos;
                double ad = (double)a;
                loss += -0.5 * ((double)npos * (ad - 1.0) + (double)nneg * ad);
                parent[small] = (unsigned short)big;
                size_[big] = (unsigned short)(su + sv);
                nz_[big]   = (unsigned short)(tu + tv);
            }
            __syncwarp(FULL);  // make merge writes visible before next edge
        }
    }
    if (lane == 0) g_loss[b] = loss;
}

__global__ void finalize_kernel(float* out) {
    out[0] = (float)(g_loss[0] + g_loss[1]);
}

// ---------------- launch -------------------------------------------------
extern "C" void kernel_launch(void* const* d_in, const int* in_sizes, int n_in,
                              void* d_out, int out_size) {
    const float* aff = (const float*)d_in[0];
    const void*  gt  = d_in[1];
    (void)in_sizes; (void)n_in; (void)out_size;

    detect_kernel<<<1, 256>>>((const int*)gt);
    init_kernel<<<(BB * NN + 255) / 256, 256>>>(gt);
    sort_kernel<<<BB, 1024>>>(aff);
    kruskal_kernel<<<BB, 32>>>();
    finalize_kernel<<<1, 1>>>((float*)d_out);
}

// round 5
// speedup vs baseline: 4.8353x; 4.8353x over previous
#include <cuda_runtime.h>
#include <cuda_bf16.h>

// Problem constants
#define HH 128
#define WW 128
#define NN (HH*WW)          // 16384 nodes per batch
#define EE (2*NN)           // 32768 edges per batch
#define BB 2
#define NBUCK 4096
#define FULLM 0xffffffffu

// ---------------- device globals (no allocation allowed) ----------------
__device__ unsigned long long g_sorted[BB][EE];   // (aff_bits<<32)|edge_idx, ascending
__device__ double g_loss[BB];

// Shared layout (dynamic):
//   u16 parent[NN]     32KB
//   u16 size [NN]      32KB
//   u16 nz   [NN]      32KB
//   u32 hist [NBUCK]   16KB
//   u32 offs [NBUCK+1] 16KB
//   u32 warp_sums[32], labcnt[64], flag
#define SMEM_U32_EXTRA (32 + 64 + 4)
#define SMEM_BYTES (3*NN*2 + (NBUCK + NBUCK + 1 + SMEM_U32_EXTRA) * 4)

extern __shared__ unsigned char smem_raw[];

__global__ void __launch_bounds__(1024) malis_kernel(const float* __restrict__ aff,
                                                     const void* __restrict__ gt) {
    int b   = blockIdx.x;
    int tid = threadIdx.x;

    unsigned short* parent = (unsigned short*)smem_raw;
    unsigned short* size_  = parent + NN;
    unsigned short* nz_    = size_ + NN;
    unsigned* hist      = (unsigned*)(nz_ + NN);
    unsigned* offs      = hist + NBUCK;
    unsigned* warp_sums = offs + NBUCK + 1;
    unsigned* labcnt    = warp_sums + 32;
    unsigned* flag      = labcnt + 64;

    // ---- detect int64 vs int32 groundtruth (labels < 64 -> odd words zero) ----
    if (tid == 0) flag[0] = 0;
    for (int i = tid; i < 64; i += 1024) labcnt[i] = 0;
    __syncthreads();
    {
        const int* g32 = (const int*)gt;
        int any = g32[2 * tid + 1];          // first 1024 entries
        if (any) atomicOr(&flag[0], 1u);
    }
    __syncthreads();
    int is64 = (flag[0] == 0);

    // ---- init union-find + label histogram ----
    for (int n = tid; n < NN; n += 1024) {
        int l = is64 ? (int)((const long long*)gt)[b * NN + n]
                     : ((const int*)gt)[b * NN + n];
        parent[n] = (unsigned short)n;
        size_[n]  = 1;
        nz_[n]    = (l != 0) ? 1 : 0;
        if (l) atomicAdd(&labcnt[l], 1u);
    }

    // ---- bucket sort of edges (ascending by (aff_bits, idx)) ----
    const float* a = aff + b * EE;
    for (int i = tid; i < NBUCK; i += 1024) hist[i] = 0;
    __syncthreads();

    for (int e = tid; e < EE; e += 1024) {
        int bk = min(NBUCK - 1, (int)(a[e] * (float)NBUCK));
        atomicAdd(&hist[bk], 1u);
    }
    __syncthreads();

    // exclusive scan of hist[4096], 4 buckets per thread
    unsigned s0 = hist[4*tid], s1 = hist[4*tid+1], s2 = hist[4*tid+2], s3 = hist[4*tid+3];
    unsigned tsum = s0 + s1 + s2 + s3;
    unsigned inc = tsum;
    #pragma unroll
    for (int o = 1; o < 32; o <<= 1) {
        unsigned v = __shfl_up_sync(FULLM, inc, o);
        if ((tid & 31) >= o) inc += v;
    }
    if ((tid & 31) == 31) warp_sums[tid >> 5] = inc;
    __syncthreads();
    if (tid < 32) {
        unsigned v = warp_sums[tid];
        unsigned iv = v;
        #pragma unroll
        for (int o = 1; o < 32; o <<= 1) {
            unsigned t2 = __shfl_up_sync(FULLM, iv, o);
            if (tid >= o) iv += t2;
        }
        warp_sums[tid] = iv - v;  // exclusive warp base
    }
    __syncthreads();
    unsigned base0 = warp_sums[tid >> 5] + inc - tsum;
    offs[4*tid]   = base0;
    offs[4*tid+1] = base0 + s0;
    offs[4*tid+2] = base0 + s0 + s1;
    offs[4*tid+3] = base0 + s0 + s1 + s2;
    __syncthreads();
    for (int i = tid; i < NBUCK; i += 1024) hist[i] = offs[i];  // scatter cursors
    if (tid == 0) offs[NBUCK] = EE;
    __syncthreads();

    unsigned long long* arr = g_sorted[b];
    for (int e = tid; e < EE; e += 1024) {
        float av = a[e];
        int bk = min(NBUCK - 1, (int)(av * (float)NBUCK));
        unsigned pos = atomicAdd(&hist[bk], 1u);
        arr[pos] = ((unsigned long long)__float_as_uint(av) << 32) | (unsigned)e;
    }
    __syncthreads();

    // per-bucket insertion sort (ascending)
    for (int bk = tid; bk < NBUCK; bk += 1024) {
        int s = (int)offs[bk], epos = (int)offs[bk + 1];
        for (int k = s + 1; k < epos; k++) {
            unsigned long long key = arr[k];
            int j = k - 1;
            while (j >= s && arr[j] > key) { arr[j + 1] = arr[j]; j--; }
            arr[j + 1] = key;
        }
    }
    __syncthreads();

    // ---- speculative batched Kruskal: warp 0 only ----
    // loss contribution per merge: tu*tv*a  (n_pos telescopes to sum_l C(n_l,2))
    if (tid < 32) {
        int lane = tid;
        double sum_wa = 0.0;
        int nmerges = 0;
        unsigned long long pk = arr[EE - 32 + lane];

        for (int base = EE - 32; base >= 0; base -= 32) {
            unsigned long long pk_next = (base >= 32) ? arr[base - 32 + lane] : 0ull;

            unsigned idx = (unsigned)pk;
            int c  = (int)(idx >> 14);
            int uu = (int)(idx & (NN - 1));
            int vv = (c == 0) ? ((uu < NN - WW) ? uu + WW : -1)
                              : (((uu & (WW - 1)) != WW - 1) ? uu + 1 : -1);
            int r_u = 0, r_v = 0;
            bool valid = (vv >= 0);
            if (valid) {
                // parallel speculative finds with path halving (benign races)
                int x = uu, p = parent[x];
                while (p != x) {
                    int g2 = parent[p];
                    parent[x] = (unsigned short)g2;
                    x = g2; p = parent[x];
                }
                r_u = x;
                x = vv; p = parent[x];
                while (p != x) {
                    int g2 = parent[p];
                    parent[x] = (unsigned short)g2;
                    x = g2; p = parent[x];
                }
                r_v = x;
            }
            unsigned cand = __ballot_sync(FULLM, valid && (r_u != r_v));
            if (cand) {
                unsigned abits_l = (unsigned)(pk >> 32);
                // resolve candidates in descending affinity order (lane 31 .. 0)
                while (cand) {
                    int i = 31 - __clz(cand);
                    cand &= ~(1u << i);
                    int ru = __shfl_sync(FULLM, r_u, i);
                    int rv = __shfl_sync(FULLM, r_v, i);
                    unsigned ab = __shfl_sync(FULLM, abits_l, i);
                    if (lane == 0) {
                        // climb to current roots (usually 0 hops)
                        int pu = parent[ru], pv = parent[rv];
                        while (pu != ru) { ru = pu; pu = parent[ru]; }
                        while (pv != rv) { rv = pv; pv = parent[rv]; }
                        if (ru != rv) {
                            int su = size_[ru], sv = size_[rv];
                            int tu = nz_[ru],  tv = nz_[rv];
                            sum_wa += (double)(tu * tv) * (double)__uint_as_float(ab);
                            int big   = (su >= sv) ? ru : rv;
                            int small = ru + rv - big;
                            parent[small] = (unsigned short)big;
                            size_[big]    = (unsigned short)(su + sv);
                            nz_[big]      = (unsigned short)(tu + tv);
                            nmerges++;
                        }
                    }
                }
                __syncwarp(FULLM);
                int nm = __shfl_sync(FULLM, nmerges, 0);
                if (nm == NN - 1) break;   // MST complete: remaining edges contribute 0
            }
            pk = pk_next;
        }

        if (lane == 0) {
            unsigned long long pairs = 0;
            for (int l = 1; l < 64; l++) {
                unsigned long long n = labcnt[l];
                pairs += n * (n - 1) / 2;
            }
            g_loss[b] = 0.5 * ((double)pairs - sum_wa);
        }
    }
}

__global__ void finalize_kernel(float* out) {
    out[0] = (float)(g_loss[0] + g_loss[1]);
}

// ---------------- launch -------------------------------------------------
extern "C" void kernel_launch(void* const* d_in, const int* in_sizes, int n_in,
                              void* d_out, int out_size) {
    const float* aff = (const float*)d_in[0];
    const void*  gt  = d_in[1];
    (void)in_sizes; (void)n_in; (void)out_size;

    cudaFuncSetAttribute(malis_kernel,
                         cudaFuncAttributeMaxDynamicSharedMemorySize, SMEM_BYTES);
    malis_kernel<<<BB, 1024, SMEM_BYTES>>>(aff, gt);
    finalize_kernel<<<1, 1>>>((float*)d_out);
}

// round 8
// speedup vs baseline: 11.4439x; 2.3668x over previous
#include <cuda_runtime.h>
#include <cuda_bf16.h>

// Problem constants
#define HH 128
#define WW 128
#define NN (HH*WW)          // 16384 nodes per batch
#define EE (2*NN)           // 32768 edges per batch
#define BB 2
#define NBUCK 4096
#define FULLM 0xffffffffu

// ---------------- device globals (no allocation allowed) ----------------
__device__ unsigned long long g_sorted[BB][EE];   // (aff_bits<<32)|edge_idx, ascending
__device__ double g_loss[BB];

// Shared layout (dynamic), u32-aligned first:
//   u32 info [NN]      64KB   (size | nz<<16)
//   u32 hist [NBUCK]   16KB   (sort cursors, then claim-hash)
//   u32 offs [NBUCK+1] 16KB
//   u32 warp_sums[32], labcnt[64], flag[1]
//   u16 parent[NN]     32KB
#define SMEM_BYTES ((NN + NBUCK + (NBUCK+1) + 32 + 64 + 1) * 4 + NN * 2)

extern __shared__ unsigned char smem_raw[];

__global__ void __launch_bounds__(1024) malis_kernel(const float* __restrict__ aff,
                                                     const void* __restrict__ gt) {
    int b   = blockIdx.x;
    int tid = threadIdx.x;

    unsigned* info      = (unsigned*)smem_raw;
    unsigned* hist      = info + NN;
    unsigned* offs      = hist + NBUCK;
    unsigned* warp_sums = offs + NBUCK + 1;
    unsigned* labcnt    = warp_sums + 32;
    unsigned* flag      = labcnt + 64;
    unsigned short* parent = (unsigned short*)(flag + 1);

    // ---- detect int64 vs int32 groundtruth (labels < 64 -> odd words zero) ----
    if (tid == 0) flag[0] = 0;
    for (int i = tid; i < 64; i += 1024) labcnt[i] = 0;
    __syncthreads();
    {
        const int* g32 = (const int*)gt;
        if (g32[2 * tid + 1]) atomicOr(&flag[0], 1u);
    }
    __syncthreads();
    int is64 = (flag[0] == 0);

    // ---- init union-find + label histogram ----
    for (int n = tid; n < NN; n += 1024) {
        int l = is64 ? (int)((const long long*)gt)[b * NN + n]
                     : ((const int*)gt)[b * NN + n];
        parent[n] = (unsigned short)n;
        info[n]   = 1u | ((l != 0) ? (1u << 16) : 0u);
        if (l) atomicAdd(&labcnt[l], 1u);
    }

    // ---- bucket sort of edges (ascending by (aff_bits, idx)) ----
    const float* a = aff + b * EE;
    for (int i = tid; i < NBUCK; i += 1024) hist[i] = 0;
    __syncthreads();

    for (int e = tid; e < EE; e += 1024) {
        int bk = min(NBUCK - 1, (int)(a[e] * (float)NBUCK));
        atomicAdd(&hist[bk], 1u);
    }
    __syncthreads();

    // exclusive scan of hist[4096], 4 buckets per thread
    unsigned s0 = hist[4*tid], s1 = hist[4*tid+1], s2 = hist[4*tid+2], s3 = hist[4*tid+3];
    unsigned tsum = s0 + s1 + s2 + s3;
    unsigned inc = tsum;
    #pragma unroll
    for (int o = 1; o < 32; o <<= 1) {
        unsigned v = __shfl_up_sync(FULLM, inc, o);
        if ((tid & 31) >= o) inc += v;
    }
    if ((tid & 31) == 31) warp_sums[tid >> 5] = inc;
    __syncthreads();
    if (tid < 32) {
        unsigned v = warp_sums[tid];
        unsigned iv = v;
        #pragma unroll
        for (int o = 1; o < 32; o <<= 1) {
            unsigned t2 = __shfl_up_sync(FULLM, iv, o);
            if (tid >= o) iv += t2;
        }
        warp_sums[tid] = iv - v;  // exclusive warp base
    }
    __syncthreads();
    unsigned base0 = warp_sums[tid >> 5] + inc - tsum;
    offs[4*tid]   = base0;
    offs[4*tid+1] = base0 + s0;
    offs[4*tid+2] = base0 + s0 + s1;
    offs[4*tid+3] = base0 + s0 + s1 + s2;
    __syncthreads();
    for (int i = tid; i < NBUCK; i += 1024) hist[i] = offs[i];  // scatter cursors
    if (tid == 0) offs[NBUCK] = EE;
    __syncthreads();

    unsigned long long* arr = g_sorted[b];
    for (int e = tid; e < EE; e += 1024) {
        float av = a[e];
        int bk = min(NBUCK - 1, (int)(av * (float)NBUCK));
        unsigned pos = atomicAdd(&hist[bk], 1u);
        arr[pos] = ((unsigned long long)__float_as_uint(av) << 32) | (unsigned)e;
    }
    __syncthreads();

    // reset hist -> claim hash for the merge phase
    for (int i = tid; i < NBUCK; i += 1024) hist[i] = 0;

    // per-bucket insertion sort (ascending)
    for (int bk = tid; bk < NBUCK; bk += 1024) {
        int s = (int)offs[bk], epos = (int)offs[bk + 1];
        for (int k = s + 1; k < epos; k++) {
            unsigned long long key = arr[k];
            int j = k - 1;
            while (j >= s && arr[j] > key) { arr[j + 1] = arr[j]; j--; }
            arr[j + 1] = key;
        }
    }
    __syncthreads();

    // ---- speculative batched Kruskal with conflict-free parallel merges ----
    // per-merge contribution: tu*tv*a   (n_pos telescopes to sum_l C(n_l,2))
    if (tid < 32) {
        int lane = tid;
        double acc = 0.0;
        int nmerges = 0;
        unsigned long long pk = arr[EE - 32 + lane];

        for (int base = EE - 32; base >= 0; base -= 32) {
            unsigned long long pk_next = (base >= 32) ? arr[base - 32 + lane] : 0ull;

            unsigned idx = (unsigned)pk;
            int c  = (int)(idx >> 14);
            int uu = (int)(idx & (NN - 1));
            int vv = (c == 0) ? ((uu < NN - WW) ? uu + WW : -1)
                              : (((uu & (WW - 1)) != WW - 1) ? uu + 1 : -1);
            int ru = 0, rv = 0;
            bool valid = (vv >= 0);
            if (valid) {
                // speculative finds with path halving (benign warp races)
                int x = uu, p = parent[x];
                while (p != x) {
                    int g2 = parent[p];
                    parent[x] = (unsigned short)g2;
                    x = g2; p = parent[x];
                }
                ru = x;
                x = vv; p = parent[x];
                while (p != x) {
                    int g2 = parent[p];
                    parent[x] = (unsigned short)g2;
                    x = g2; p = parent[x];
                }
                rv = x;
            }
            bool cnd = valid && (ru != rv);
            unsigned cand = __ballot_sync(FULLM, cnd);
            if (cand) {
                unsigned prio = (unsigned)(lane + 1);
                unsigned h1 = 0, h2 = 0;
                if (cnd) {
                    h1 = (unsigned)ru & (NBUCK - 1);
                    h2 = (unsigned)rv & (NBUCK - 1);
                    atomicMax(&hist[h1], prio);
                    atomicMax(&hist[h2], prio);
                }
                __syncwarp(FULLM);
                bool par = false;
                if (cnd) par = (hist[h1] == prio) && (hist[h2] == prio);
                unsigned parmask = __ballot_sync(FULLM, par);

                if (par) {
                    // conflict-free: merge in parallel, one lane per edge
                    unsigned iu = info[ru], iv = info[rv];
                    int su = (int)(iu & 0xffffu), sv = (int)(iv & 0xffffu);
                    int tu = (int)(iu >> 16),    tv = (int)(iv >> 16);
                    acc += (double)(tu * tv) * (double)__uint_as_float((unsigned)(pk >> 32));
                    int big   = (su >= sv) ? ru : rv;
                    int small = ru + rv - big;
                    parent[small] = (unsigned short)big;
                    info[big] = iu + iv;   // packed u16 adds, no carry (<=16384)
                }
                __syncwarp(FULLM);
                nmerges += __popc(parmask);

                // serial fallback for conflicting candidates, descending order
                unsigned def = cand & ~parmask;
                int smerged = 0;
                while (def) {
                    int i = 31 - __clz((int)def);
                    def &= ~(1u << i);
                    int rru = __shfl_sync(FULLM, ru, i);
                    int rrv = __shfl_sync(FULLM, rv, i);
                    unsigned ab = __shfl_sync(FULLM, (unsigned)(pk >> 32), i);
                    if (lane == 0) {
                        int pu = parent[rru], pv = parent[rrv];
                        while (pu != rru) { rru = pu; pu = parent[rru]; }
                        while (pv != rrv) { rrv = pv; pv = parent[rrv]; }
                        if (rru != rrv) {
                            unsigned iu = info[rru], iv = info[rrv];
                            int su = (int)(iu & 0xffffu), sv = (int)(iv & 0xffffu);
                            int tu = (int)(iu >> 16),    tv = (int)(iv >> 16);
                            acc += (double)(tu * tv) * (double)__uint_as_float(ab);
                            int big   = (su >= sv) ? rru : rrv;
                            int small = rru + rrv - big;
                            parent[small] = (unsigned short)big;
                            info[big] = iu + iv;
                            smerged++;
                        }
                    }
                }
                __syncwarp(FULLM);
                nmerges += __shfl_sync(FULLM, smerged, 0);

                // reset claim slots
                if (cnd) { hist[h1] = 0; hist[h2] = 0; }
                __syncwarp(FULLM);

                if (nmerges == NN - 1) break;   // MST complete: rest contribute 0
            }
            pk = pk_next;
        }

        // reduce per-lane accumulators
        #pragma unroll
        for (int o = 16; o; o >>= 1)
            acc += __shfl_down_sync(FULLM, acc, o);

        if (lane == 0) {
            unsigned long long pairs = 0;
            for (int l = 1; l < 64; l++) {
                unsigned long long n = labcnt[l];
                pairs += n * (n - 1) / 2;
            }
            g_loss[b] = 0.5 * ((double)pairs - acc);
        }
    }
}

__global__ void finalize_kernel(float* out) {
    out[0] = (float)(g_loss[0] + g_loss[1]);
}

// ---------------- launch -------------------------------------------------
extern "C" void kernel_launch(void* const* d_in, const int* in_sizes, int n_in,
                              void* d_out, int out_size) {
    const float* aff = (const float*)d_in[0];
    const void*  gt  = d_in[1];
    (void)in_sizes; (void)n_in; (void)out_size;

    cudaFuncSetAttribute(malis_kernel,
                         cudaFuncAttributeMaxDynamicSharedMemorySize, SMEM_BYTES);
    malis_kernel<<<BB, 1024, SMEM_BYTES>>>(aff, gt);
    finalize_kernel<<<1, 1>>>((float*)d_out);
}

// round 11
// speedup vs baseline: 23.9377x; 2.0917x over previous
#include <cuda_runtime.h>
#include <cuda_bf16.h>

// Problem constants
#define HH 128
#define WW 128
#define NN (HH*WW)          // 16384 nodes per batch
#define EE (2*NN)           // 32768 edges per batch
#define BB 2
#define NBUCK 4096
#define WWIN 1024           // filter window (1 edge per thread)
#define FULLM 0xffffffffu

// ---------------- device globals (no allocation allowed) ----------------
__device__ unsigned long long g_sorted[BB][EE];   // (aff_bits<<32)|edge_idx, ascending
__device__ double g_loss[BB];

// Shared layout (dynamic), u32 first:
//   u32 info [NN]        64KB  (size | nz<<16)
//   u32 hist [NBUCK]     16KB  (sort cursors, then claim table)
//   u32 offs [NBUCK+1]   16KB
//   u32 warp_sums[32], labcnt[64], misc[4]
//   u32 caff  [WWIN]      4KB  (compacted candidate affinities)
//   u32 croots[WWIN]      4KB  (compacted candidate roots, ru|rv<<16)
//   u16 parent[NN]       32KB
#define SMEM_BYTES ((NN + NBUCK + (NBUCK+1) + 32 + 64 + 4 + WWIN + WWIN) * 4 + NN * 2)

extern __shared__ unsigned char smem_raw[];

__global__ void __launch_bounds__(1024) malis_kernel(const float* __restrict__ aff,
                                                     const void* __restrict__ gt) {
    int b    = blockIdx.x;
    int tid  = threadIdx.x;
    int lane = tid & 31;
    int wid  = tid >> 5;

    unsigned* info      = (unsigned*)smem_raw;
    unsigned* hist      = info + NN;
    unsigned* offs      = hist + NBUCK;
    unsigned* warp_sums = offs + NBUCK + 1;
    unsigned* labcnt    = warp_sums + 32;
    unsigned* misc      = labcnt + 64;           // [0]=detect/done  [1]=ncand
    unsigned* caff      = misc + 4;
    unsigned* croots    = caff + WWIN;
    unsigned short* parent = (unsigned short*)(croots + WWIN);

    // ---- detect int64 vs int32 groundtruth (labels < 64 -> odd words zero) ----
    if (tid == 0) misc[0] = 0;
    for (int i = tid; i < 64; i += 1024) labcnt[i] = 0;
    __syncthreads();
    {
        const int* g32 = (const int*)gt;
        if (g32[2 * tid + 1]) atomicOr(&misc[0], 1u);
    }
    __syncthreads();
    int is64 = (misc[0] == 0);

    // ---- init union-find + label histogram ----
    for (int n = tid; n < NN; n += 1024) {
        int l = is64 ? (int)((const long long*)gt)[b * NN + n]
                     : ((const int*)gt)[b * NN + n];
        parent[n] = (unsigned short)n;
        info[n]   = 1u | ((l != 0) ? (1u << 16) : 0u);
        if (l) atomicAdd(&labcnt[l], 1u);
    }

    // ---- bucket sort of edges (ascending by (aff_bits, idx)) ----
    const float* a = aff + b * EE;
    for (int i = tid; i < NBUCK; i += 1024) hist[i] = 0;
    __syncthreads();

    for (int e = tid; e < EE; e += 1024) {
        int bk = min(NBUCK - 1, (int)(a[e] * (float)NBUCK));
        atomicAdd(&hist[bk], 1u);
    }
    __syncthreads();

    // exclusive scan of hist[4096], 4 buckets per thread
    unsigned s0 = hist[4*tid], s1 = hist[4*tid+1], s2 = hist[4*tid+2], s3 = hist[4*tid+3];
    unsigned tsum = s0 + s1 + s2 + s3;
    unsigned inc = tsum;
    #pragma unroll
    for (int o = 1; o < 32; o <<= 1) {
        unsigned v = __shfl_up_sync(FULLM, inc, o);
        if (lane >= o) inc += v;
    }
    if (lane == 31) warp_sums[wid] = inc;
    __syncthreads();
    if (tid < 32) {
        unsigned v = warp_sums[tid];
        unsigned iv = v;
        #pragma unroll
        for (int o = 1; o < 32; o <<= 1) {
            unsigned t2 = __shfl_up_sync(FULLM, iv, o);
            if (tid >= o) iv += t2;
        }
        warp_sums[tid] = iv - v;  // exclusive warp base
    }
    __syncthreads();
    unsigned base0 = warp_sums[wid] + inc - tsum;
    offs[4*tid]   = base0;
    offs[4*tid+1] = base0 + s0;
    offs[4*tid+2] = base0 + s0 + s1;
    offs[4*tid+3] = base0 + s0 + s1 + s2;
    __syncthreads();
    for (int i = tid; i < NBUCK; i += 1024) hist[i] = offs[i];  // scatter cursors
    if (tid == 0) offs[NBUCK] = EE;
    __syncthreads();

    unsigned long long* arr = g_sorted[b];
    for (int e = tid; e < EE; e += 1024) {
        float av = a[e];
        int bk = min(NBUCK - 1, (int)(av * (float)NBUCK));
        unsigned pos = atomicAdd(&hist[bk], 1u);
        arr[pos] = ((unsigned long long)__float_as_uint(av) << 32) | (unsigned)e;
    }
    __syncthreads();

    // reset hist -> claim table for the resolve phase
    for (int i = tid; i < NBUCK; i += 1024) hist[i] = 0;

    // per-bucket insertion sort (ascending)
    for (int bk = tid; bk < NBUCK; bk += 1024) {
        int s = (int)offs[bk], epos = (int)offs[bk + 1];
        for (int k = s + 1; k < epos; k++) {
            unsigned long long key = arr[k];
            int j = k - 1;
            while (j >= s && arr[j] > key) { arr[j + 1] = arr[j]; j--; }
            arr[j + 1] = key;
        }
    }
    if (tid == 0) misc[0] = 0;   // done flag
    __syncthreads();

    // ==== windowed Kruskal: block-parallel filter + warp-0 compacted resolve ====
    // per-merge contribution: tu*tv*a   (n_pos telescopes to sum_l C(n_l,2))
    double acc = 0.0;       // meaningful in warp 0 lanes
    int nmerges = 0;        // tracked consistently in all warp-0 lanes

    for (int wbase = EE - WWIN; wbase >= 0; wbase -= WWIN) {
        // ---- filter: 1 edge per thread, finds with path halving (forest static) ----
        unsigned long long pk = arr[wbase + tid];
        unsigned idx = (unsigned)pk;
        int c  = (int)(idx >> 14);
        int uu = (int)(idx & (NN - 1));
        int vv = (c == 0) ? ((uu < NN - WW) ? uu + WW : -1)
                          : (((uu & (WW - 1)) != WW - 1) ? uu + 1 : -1);
        int ru = 0, rv = 0;
        bool cnd = false;
        if (vv >= 0) {
            int x = uu, p = parent[x];
            while (p != x) {
                int g2 = parent[p];
                parent[x] = (unsigned short)g2;
                x = g2; p = parent[x];
            }
            ru = x;
            x = vv; p = parent[x];
            while (p != x) {
                int g2 = parent[p];
                parent[x] = (unsigned short)g2;
                x = g2; p = parent[x];
            }
            rv = x;
            cnd = (ru != rv);
        }
        unsigned wmask = __ballot_sync(FULLM, cnd);
        if (lane == 0) warp_sums[wid] = __popc(wmask);
        __syncthreads();
        if (tid < 32) {
            unsigned v = warp_sums[tid], iv = v;
            #pragma unroll
            for (int o = 1; o < 32; o <<= 1) {
                unsigned t2 = __shfl_up_sync(FULLM, iv, o);
                if (tid >= o) iv += t2;
            }
            warp_sums[tid] = iv - v;
            if (tid == 31) misc[1] = iv;   // ncand
        }
        __syncthreads();
        int ncand = (int)misc[1];
        if (cnd) {
            int r = (int)warp_sums[wid] + __popc(wmask & ((1u << lane) - 1));
            croots[r] = (unsigned)ru | ((unsigned)rv << 16);
            caff[r]   = (unsigned)(pk >> 32);
        }
        __syncthreads();

        // ---- resolve: warp 0 only, descending affinity = descending rank ----
        if (wid == 0 && ncand) {
            for (int cb = 0; cb < ncand; cb += 32) {
                int j = ncand - 1 - cb - lane;   // lane 0 = highest affinity in chunk
                bool has = (j >= 0);
                int rru = 0, rrv = 0;
                unsigned ab = 0;
                if (has) {
                    unsigned pr = croots[j];
                    rru = (int)(pr & 0xffffu);
                    rrv = (int)(pr >> 16);
                    ab  = caff[j];
                    // re-climb to current roots (filter roots already compressed)
                    int p = parent[rru];
                    while (p != rru) { rru = p; p = parent[rru]; }
                    p = parent[rrv];
                    while (p != rrv) { rrv = p; p = parent[rrv]; }
                }
                bool cc = has && (rru != rrv);
                unsigned cand = __ballot_sync(FULLM, cc);
                if (!cand) continue;

                unsigned prio = 32u - (unsigned)lane;   // higher = higher affinity
                unsigned h1 = 0, h2 = 0;
                if (cc) {
                    h1 = (unsigned)rru & (NBUCK - 1);
                    h2 = (unsigned)rrv & (NBUCK - 1);
                    atomicMax(&hist[h1], prio);
                    atomicMax(&hist[h2], prio);
                }
                __syncwarp(FULLM);
                bool par = cc && (hist[h1] == prio) && (hist[h2] == prio);
                unsigned parmask = __ballot_sync(FULLM, par);

                if (par) {   // conflict-free winners merge concurrently
                    unsigned iu = info[rru], iv2 = info[rrv];
                    int su = (int)(iu & 0xffffu), sv = (int)(iv2 & 0xffffu);
                    acc += (double)((int)(iu >> 16) * (int)(iv2 >> 16))
                         * (double)__uint_as_float(ab);
                    int big   = (su >= sv) ? rru : rrv;
                    int small = rru + rrv - big;
                    parent[small] = (unsigned short)big;
                    info[big] = iu + iv2;   // packed u16 adds, no carry (<=16384)
                }
                __syncwarp(FULLM);
                nmerges += __popc(parmask);

                // serial fallback, descending affinity = ascending lane
                unsigned def = cand & ~parmask;
                int sm = 0;
                while (def) {
                    int i = __ffs(def) - 1;
                    def &= def - 1;
                    int au = __shfl_sync(FULLM, rru, i);
                    int av = __shfl_sync(FULLM, rrv, i);
                    unsigned ab2 = __shfl_sync(FULLM, ab, i);
                    if (lane == 0) {
                        int p = parent[au];
                        while (p != au) { au = p; p = parent[au]; }
                        p = parent[av];
                        while (p != av) { av = p; p = parent[av]; }
                        if (au != av) {
                            unsigned iu = info[au], iv2 = info[av];
                            int su = (int)(iu & 0xffffu), sv = (int)(iv2 & 0xffffu);
                            acc += (double)((int)(iu >> 16) * (int)(iv2 >> 16))
                                 * (double)__uint_as_float(ab2);
                            int big   = (su >= sv) ? au : av;
                            int small = au + av - big;
                            parent[small] = (unsigned short)big;
                            info[big] = iu + iv2;
                            sm++;
                        }
                    }
                }
                nmerges += __shfl_sync(FULLM, sm, 0);

                if (cc) { hist[h1] = 0; hist[h2] = 0; }   // reset claim slots
                __syncwarp(FULLM);

                if (nmerges == NN - 1) {                  // MST complete
                    if (lane == 0) misc[0] = 1;
                    break;
                }
            }
        }
        __syncthreads();
        if (misc[0]) break;   // remaining edges contribute 0
    }

    // ---- final reduction (warp 0) ----
    if (wid == 0) {
        #pragma unroll
        for (int o = 16; o; o >>= 1)
            acc += __shfl_down_sync(FULLM, acc, o);
        if (lane == 0) {
            unsigned long long pairs = 0;
            for (int l = 1; l < 64; l++) {
                unsigned long long n = labcnt[l];
                pairs += n * (n - 1) / 2;
            }
            g_loss[b] = 0.5 * ((double)pairs - acc);
        }
    }
}

__global__ void finalize_kernel(float* out) {
    out[0] = (float)(g_loss[0] + g_loss[1]);
}

// ---------------- launch -------------------------------------------------
extern "C" void kernel_launch(void* const* d_in, const int* in_sizes, int n_in,
                              void* d_out, int out_size) {
    const float* aff = (const float*)d_in[0];
    const void*  gt  = d_in[1];
    (void)in_sizes; (void)n_in; (void)out_size;

    cudaFuncSetAttribute(malis_kernel,
                         cudaFuncAttributeMaxDynamicSharedMemorySize, SMEM_BYTES);
    malis_kernel<<<BB, 1024, SMEM_BYTES>>>(aff, gt);
    finalize_kernel<<<1, 1>>>((float*)d_out);
}